// round 3
// baseline (speedup 1.0000x reference)
#include <cuda_runtime.h>

#define BATCH 128
#define SEQ   512
#define DIM   768
#define MAXC  64
#define NTHREADS 512
#define NWARPS (NTHREADS / 32)

__global__ __launch_bounds__(NTHREADS, 1)
void summarizer_kernel(const float* __restrict__ enc,
                       const float* __restrict__ W,
                       const float* __restrict__ bias,
                       const int* __restrict__ cls,
                       float* __restrict__ out) {
    __shared__ float sW[DIM];
    __shared__ int   sidx[MAXC];
    __shared__ int   warpCnt[NWARPS];
    __shared__ int   warpOff[NWARPS];

    const int b    = blockIdx.x;
    const int tid  = threadIdx.x;
    const int lane = tid & 31;
    const int warp = tid >> 5;

    // Load W into shared (768 floats, coalesced).
    for (int i = tid; i < DIM; i += NTHREADS) sW[i] = W[i];
    if (tid < MAXC) sidx[tid] = -1;

    // Phase 1: find the first <=64 cls positions. One thread per position.
    const bool flag = cls[b * SEQ + tid] != 0;
    const unsigned bal = __ballot_sync(0xffffffffu, flag);
    const int laneRank = __popc(bal & ((1u << lane) - 1u));
    if (lane == 0) warpCnt[warp] = __popc(bal);
    __syncthreads();

    if (warp == 0 && lane < NWARPS) {
        int v = warpCnt[lane];
        int s = v;
        #pragma unroll
        for (int off = 1; off < NWARPS; off <<= 1) {
            int n = __shfl_up_sync(0x0000ffffu, s, off);
            if (lane >= off) s += n;
        }
        warpOff[lane] = s - v;  // exclusive prefix
    }
    __syncthreads();

    if (flag) {
        int r = warpOff[warp] + laneRank;
        if (r < MAXC) sidx[r] = tid;   // token position in sequence
    }
    __syncthreads();

    const float bv = bias[0];

    // Phase 2: 64 dot products, 4 rows per warp.
    #pragma unroll
    for (int r = warp; r < MAXC; r += NWARPS) {
        const int pos = sidx[r];
        float sum = 0.0f;
        if (pos >= 0) {
            const float4* row = reinterpret_cast<const float4*>(
                enc + ((size_t)b * SEQ + pos) * DIM);
            const float4* w4 = reinterpret_cast<const float4*>(sW);
            // 192 float4 per row; 6 per lane — front-batch loads for MLP.
            float4 a0 = row[lane +   0];
            float4 a1 = row[lane +  32];
            float4 a2 = row[lane +  64];
            float4 a3 = row[lane +  96];
            float4 a4 = row[lane + 128];
            float4 a5 = row[lane + 160];
            float4 w0 = w4[lane +   0];
            float4 w1 = w4[lane +  32];
            float4 w2 = w4[lane +  64];
            float4 w3 = w4[lane +  96];
            float4 w4v = w4[lane + 128];
            float4 w5 = w4[lane + 160];
            sum += a0.x*w0.x + a0.y*w0.y + a0.z*w0.z + a0.w*w0.w;
            sum += a1.x*w1.x + a1.y*w1.y + a1.z*w1.z + a1.w*w1.w;
            sum += a2.x*w2.x + a2.y*w2.y + a2.z*w2.z + a2.w*w2.w;
            sum += a3.x*w3.x + a3.y*w3.y + a3.z*w3.z + a3.w*w3.w;
            sum += a4.x*w4v.x + a4.y*w4v.y + a4.z*w4v.z + a4.w*w4v.w;
            sum += a5.x*w5.x + a5.y*w5.y + a5.z*w5.z + a5.w*w5.w;
        }
        // Warp reduction.
        #pragma unroll
        for (int off = 16; off > 0; off >>= 1)
            sum += __shfl_down_sync(0xffffffffu, sum, off);
        if (lane == 0) {
            float z = sum + bv;               // invalid slot: sum=0 -> sigmoid(bias)
            out[b * MAXC + r] = 1.0f / (1.0f + expf(-z));
        }
    }
}

extern "C" void kernel_launch(void* const* d_in, const int* in_sizes, int n_in,
                              void* d_out, int out_size) {
    const float* enc  = (const float*)d_in[0];
    const float* W    = (const float*)d_in[1];
    const float* bias = (const float*)d_in[2];
    const int*   cls  = (const int*)d_in[3];
    float* out = (float*)d_out;

    summarizer_kernel<<<BATCH, NTHREADS>>>(enc, W, bias, cls, out);
}

// round 4
// speedup vs baseline: 1.2905x; 1.2905x over previous
#include <cuda_runtime.h>

#define BATCH 128
#define SEQ   512
#define DIM   768
#define MAXC  64
#define NT    128           // threads per CTA (4 warps)
#define GROUPS 8            // CTAs per batch
#define ROWS_PER_CTA (MAXC / GROUPS)   // 8 rows, 2 per warp

__global__ __launch_bounds__(NT)
void summarizer_kernel(const float* __restrict__ enc,
                       const float* __restrict__ W,
                       const float* __restrict__ bias,
                       const int* __restrict__ cls,
                       float* __restrict__ out) {
    __shared__ int sidx[MAXC];
    __shared__ int wtot[4];
    __shared__ int wbase[4];

    const int bid   = blockIdx.x;
    const int b     = bid >> 3;          // batch
    const int group = bid & 7;           // row-group within batch
    const int tid   = threadIdx.x;
    const int lane  = tid & 31;
    const int warp  = tid >> 5;

    if (tid < MAXC) sidx[tid] = -1;

    // ---- Phase 1: compact indices of first <=64 set cls positions ----
    // Each thread owns 4 consecutive positions via one int4 load.
    const int4 cv = reinterpret_cast<const int4*>(cls + (size_t)b * SEQ)[tid];
    const int f0 = (cv.x != 0), f1 = (cv.y != 0), f2 = (cv.z != 0), f3 = (cv.w != 0);
    const int cnt = f0 + f1 + f2 + f3;

    // Warp inclusive scan of per-thread counts.
    int s = cnt;
    #pragma unroll
    for (int off = 1; off < 32; off <<= 1) {
        int n = __shfl_up_sync(0xffffffffu, s, off);
        if (lane >= off) s += n;
    }
    const int laneExcl = s - cnt;
    if (lane == 31) wtot[warp] = s;
    __syncthreads();

    if (tid == 0) {
        int a = 0;
        #pragma unroll
        for (int i = 0; i < 4; i++) { wbase[i] = a; a += wtot[i]; }
    }
    __syncthreads();

    {
        int r = wbase[warp] + laneExcl;
        const int p = tid * 4;
        if (f0) { if (r < MAXC) sidx[r] = p;     r++; }
        if (f1) { if (r < MAXC) sidx[r] = p + 1; r++; }
        if (f2) { if (r < MAXC) sidx[r] = p + 2; r++; }
        if (f3) { if (r < MAXC) sidx[r] = p + 3; r++; }
    }
    __syncthreads();

    // ---- Phase 2: 2 rows per warp, loads front-batched for MLP ----
    const float4* __restrict__ w4 = reinterpret_cast<const float4*>(W);
    const float4 w0 = w4[lane +   0];
    const float4 w1 = w4[lane +  32];
    const float4 w2 = w4[lane +  64];
    const float4 w3 = w4[lane +  96];
    const float4 w4v = w4[lane + 128];
    const float4 w5 = w4[lane + 160];

    const int r0 = group * ROWS_PER_CTA + warp * 2;
    const int p0 = sidx[r0];
    const int p1 = sidx[r0 + 1];

    float s0 = 0.0f, s1 = 0.0f;

    if (p1 >= 0) {
        // Common case: both rows valid -> 12 independent LDG.128 in flight.
        const float4* ra = reinterpret_cast<const float4*>(enc + ((size_t)b * SEQ + p0) * DIM);
        const float4* rb = reinterpret_cast<const float4*>(enc + ((size_t)b * SEQ + p1) * DIM);
        float4 a0 = ra[lane +   0];
        float4 a1 = ra[lane +  32];
        float4 a2 = ra[lane +  64];
        float4 a3 = ra[lane +  96];
        float4 a4 = ra[lane + 128];
        float4 a5 = ra[lane + 160];
        float4 b0 = rb[lane +   0];
        float4 b1 = rb[lane +  32];
        float4 b2 = rb[lane +  64];
        float4 b3 = rb[lane +  96];
        float4 b4 = rb[lane + 128];
        float4 b5 = rb[lane + 160];
        s0 += a0.x*w0.x + a0.y*w0.y + a0.z*w0.z + a0.w*w0.w;
        s0 += a1.x*w1.x + a1.y*w1.y + a1.z*w1.z + a1.w*w1.w;
        s0 += a2.x*w2.x + a2.y*w2.y + a2.z*w2.z + a2.w*w2.w;
        s0 += a3.x*w3.x + a3.y*w3.y + a3.z*w3.z + a3.w*w3.w;
        s0 += a4.x*w4v.x + a4.y*w4v.y + a4.z*w4v.z + a4.w*w4v.w;
        s0 += a5.x*w5.x + a5.y*w5.y + a5.z*w5.z + a5.w*w5.w;
        s1 += b0.x*w0.x + b0.y*w0.y + b0.z*w0.z + b0.w*w0.w;
        s1 += b1.x*w1.x + b1.y*w1.y + b1.z*w1.z + b1.w*w1.w;
        s1 += b2.x*w2.x + b2.y*w2.y + b2.z*w2.z + b2.w*w2.w;
        s1 += b3.x*w3.x + b3.y*w3.y + b3.z*w3.z + b3.w*w3.w;
        s1 += b4.x*w4v.x + b4.y*w4v.y + b4.z*w4v.z + b4.w*w4v.w;
        s1 += b5.x*w5.x + b5.y*w5.y + b5.z*w5.z + b5.w*w5.w;
    } else if (p0 >= 0) {
        const float4* ra = reinterpret_cast<const float4*>(enc + ((size_t)b * SEQ + p0) * DIM);
        float4 a0 = ra[lane +   0];
        float4 a1 = ra[lane +  32];
        float4 a2 = ra[lane +  64];
        float4 a3 = ra[lane +  96];
        float4 a4 = ra[lane + 128];
        float4 a5 = ra[lane + 160];
        s0 += a0.x*w0.x + a0.y*w0.y + a0.z*w0.z + a0.w*w0.w;
        s0 += a1.x*w1.x + a1.y*w1.y + a1.z*w1.z + a1.w*w1.w;
        s0 += a2.x*w2.x + a2.y*w2.y + a2.z*w2.z + a2.w*w2.w;
        s0 += a3.x*w3.x + a3.y*w3.y + a3.z*w3.z + a3.w*w3.w;
        s0 += a4.x*w4v.x + a4.y*w4v.y + a4.z*w4v.z + a4.w*w4v.w;
        s0 += a5.x*w5.x + a5.y*w5.y + a5.z*w5.z + a5.w*w5.w;
    }

    // Warp reductions for both rows.
    #pragma unroll
    for (int off = 16; off > 0; off >>= 1) {
        s0 += __shfl_down_sync(0xffffffffu, s0, off);
        s1 += __shfl_down_sync(0xffffffffu, s1, off);
    }

    if (lane == 0) {
        const float bv = bias[0];
        out[b * MAXC + r0]     = 1.0f / (1.0f + expf(-(s0 + bv)));
        out[b * MAXC + r0 + 1] = 1.0f / (1.0f + expf(-(s1 + bv)));
    }
}

extern "C" void kernel_launch(void* const* d_in, const int* in_sizes, int n_in,
                              void* d_out, int out_size) {
    const float* enc  = (const float*)d_in[0];
    const float* W    = (const float*)d_in[1];
    const float* bias = (const float*)d_in[2];
    const int*   cls  = (const int*)d_in[3];
    float* out = (float*)d_out;

    summarizer_kernel<<<BATCH * GROUPS, NT>>>(enc, W, bias, cls, out);
}